// round 16
// baseline (speedup 1.0000x reference)
#include <cuda_runtime.h>
#include <cuda_fp16.h>
#include <cstdint>

// ---------------------------------------------------------------------------
// GCN: out = SpMM(relu(SpMM(X@W1+b1)) @ W2 + b2)
// R16: R15 with the 3-kernel scan replaced by ONE decoupled-lookback scan
//      (196 blocks co-resident -> spin-free-progress guaranteed). Launches
//      10 -> 8. hist block 0 re-zeros the lookback state each call.
// ---------------------------------------------------------------------------

#define MAX_NODES 100000
#define MAX_EDGES 1600000
#define FEAT 128
#define SCAN_B 512
#define SCAN_NB ((MAX_NODES + SCAN_B - 1) / SCAN_B)   // 196

#define FLAG_A 1   // aggregate published
#define FLAG_P 2   // inclusive prefix published

__device__ __align__(16) __half g_H  [(size_t)MAX_NODES * FEAT];  // GEMM out (reused)
__device__ __align__(16) __half g_S1 [(size_t)MAX_NODES * FEAT];  // relu(SpMM1)
__device__ __align__(16) __half g_W1h[256 * 128];                 // W1 in fp16
__device__ int  g_cnt[MAX_NODES];
__device__ int  g_row_start[MAX_NODES + 1];
__device__ int  g_row_next[MAX_NODES];
__device__ int  g_state[SCAN_NB];                  // lookback state
__device__ int2 g_edge[MAX_EDGES];                 // {col, float_as_int(val)}

// ---------------------------------------------------------------------------
// CSR build: hist (vec4 RED; block 0 zeroes lookback state) ->
//            scan_lookback (single pass) -> scatter (atomic ticket)
// ---------------------------------------------------------------------------
__global__ void hist_kernel(const int4* __restrict__ row4, int nE4,
                            int* __restrict__ cnt, int* __restrict__ state)
{
    if (blockIdx.x == 0 && threadIdx.x < SCAN_NB)
        state[threadIdx.x] = 0;                    // reset lookback state
    int i = blockIdx.x * blockDim.x + threadIdx.x;
    if (i < nE4) {
        int4 r = row4[i];
        atomicAdd(&cnt[r.x], 1);
        atomicAdd(&cnt[r.y], 1);
        atomicAdd(&cnt[r.z], 1);
        atomicAdd(&cnt[r.w], 1);
    }
}

// Single-pass exclusive scan with decoupled lookback. Also writes row_next
// and re-zeros cnt (invariant for the next call). row_start[n] = grand total.
__global__ __launch_bounds__(SCAN_B) void scan_lookback_kernel(
    int* __restrict__ cnt, int* __restrict__ row_start,
    int* __restrict__ row_next, int* __restrict__ state, int n)
{
    __shared__ int sh[SCAN_B];
    __shared__ int s_off;
    const int tid = threadIdx.x;
    const int b   = blockIdx.x;
    const int i   = b * SCAN_B + tid;

    int v = (i < n) ? cnt[i] : 0;
    sh[tid] = v;
    __syncthreads();
#pragma unroll
    for (int off = 1; off < SCAN_B; off <<= 1) {     // Hillis-Steele inclusive
        int t = (tid >= off) ? sh[tid - off] : 0;
        __syncthreads();
        sh[tid] += t;
        __syncthreads();
    }
    const int agg = sh[SCAN_B - 1];                  // tile total

    if (tid == 0) {
        if (b == 0) {
            __threadfence();
            atomicExch(&state[0], (FLAG_P << 28) | agg);
            s_off = 0;
        } else {
            __threadfence();
            atomicExch(&state[b], (FLAG_A << 28) | agg);
            int run = 0, idx = b - 1;
            while (true) {
                int s = atomicAdd(&state[idx], 0);
                int f = s >> 28;
                if (f == FLAG_P) { run += s & 0x0FFFFFFF; break; }
                if (f == FLAG_A) { run += s & 0x0FFFFFFF; idx--; }
                // f==0: predecessor not published yet -> spin (co-resident)
            }
            __threadfence();
            atomicExch(&state[b], (FLAG_P << 28) | (run + agg));
            s_off = run;
        }
    }
    __syncthreads();

    int excl = s_off + sh[tid] - v;
    if (i < n) {
        row_start[i] = excl;
        row_next[i]  = excl;
        cnt[i]       = 0;                            // restore for next call
    }
    if (b == gridDim.x - 1 && tid == 0)
        row_start[n] = s_off + agg;                  // grand total
}

__global__ void scatter_kernel(const int* __restrict__ row, const int* __restrict__ col,
                               const float* __restrict__ vals, int nE,
                               int* __restrict__ row_next, int2* __restrict__ edge)
{
    int i = blockIdx.x * blockDim.x + threadIdx.x;
    if (i < nE) {
        int r = row[i];
        int p = atomicAdd(&row_next[r], 1);
        edge[p] = make_int2(col[i], __float_as_int(vals[i]));
    }
}

// ---------------------------------------------------------------------------
// W1 fp32 -> fp16 preconvert
// ---------------------------------------------------------------------------
__global__ void w1_convert_kernel(const float* __restrict__ W, __half* __restrict__ Wh)
{
    int i = blockIdx.x * 256 + threadIdx.x;     // 0..8191
    float4 v = ((const float4*)W)[i];
    uint2 o;
    *(__half2*)&o.x = __floats2half2_rn(v.x, v.y);
    *(__half2*)&o.y = __floats2half2_rn(v.z, v.w);
    ((uint2*)Wh)[i] = o;
}

// ---------------------------------------------------------------------------
// HMMA primitives
// ---------------------------------------------------------------------------
__device__ __forceinline__ void mma16816(float* d, const uint32_t* a, const uint32_t* b)
{
    asm volatile(
        "mma.sync.aligned.m16n8k16.row.col.f32.f16.f16.f32 "
        "{%0,%1,%2,%3}, {%4,%5,%6,%7}, {%8,%9}, {%0,%1,%2,%3};\n"
        : "+f"(d[0]), "+f"(d[1]), "+f"(d[2]), "+f"(d[3])
        : "r"(a[0]), "r"(a[1]), "r"(a[2]), "r"(a[3]), "r"(b[0]), "r"(b[1]));
}

__device__ __forceinline__ void ldsm_x4(uint32_t* r, uint32_t addr)
{
    asm volatile("ldmatrix.sync.aligned.m8n8.x4.shared.b16 {%0,%1,%2,%3}, [%4];"
                 : "=r"(r[0]), "=r"(r[1]), "=r"(r[2]), "=r"(r[3]) : "r"(addr));
}

__device__ __forceinline__ void ldsm_x4_t(uint32_t* r, uint32_t addr)
{
    asm volatile("ldmatrix.sync.aligned.m8n8.x4.trans.shared.b16 {%0,%1,%2,%3}, [%4];"
                 : "=r"(r[0]), "=r"(r[1]), "=r"(r[2]), "=r"(r[3]) : "r"(addr));
}

#define AS_STRIDE 56
#define WS_STRIDE 136

// ---------------------------------------------------------------------------
// GEMM1 (exact R14/R15, race-fixed): A fp32 staged + convert; W fp16 direct.
// ---------------------------------------------------------------------------
__global__ __launch_bounds__(256) void gemm1_cpasync_kernel(
    const float* __restrict__ A, const __half* __restrict__ Wh,
    const float* __restrict__ bias, __half* __restrict__ C, int M)
{
    constexpr int K = 256, BM = 128, BK = 32, N = 128;
    constexpr int T = K / BK;                       // 8
    constexpr int AF_ELEMS = BM * BK;
    constexpr int WS_ELEMS = BK * WS_STRIDE;

    extern __shared__ char smem_raw[];
    float*  Af = (float*)smem_raw;
    __half* As = (__half*)(smem_raw + 2 * AF_ELEMS * 4);
    __half* Ws = (__half*)(smem_raw + 2 * AF_ELEMS * 4 + BM * AS_STRIDE * 2);

    const int tid  = threadIdx.x;
    const int lane = tid & 31;
    const int wid  = tid >> 5;
    const int wm   = wid >> 1;
    const int wn   = wid & 1;
    const int m0   = blockIdx.x * BM;

    const uint32_t sAf = (uint32_t)__cvta_generic_to_shared(Af);
    const uint32_t sAs = (uint32_t)__cvta_generic_to_shared(As);
    const uint32_t sWs = (uint32_t)__cvta_generic_to_shared(Ws);

    float acc[2][8][4];
#pragma unroll
    for (int i = 0; i < 2; i++)
#pragma unroll
        for (int j = 0; j < 8; j++)
#pragma unroll
            for (int q = 0; q < 4; q++) acc[i][j][q] = 0.f;

    auto issue_cp = [&](int t) {
        const int k0  = t * BK;
        const int buf = t & 1;
#pragma unroll
        for (int i = 0; i < 4; i++) {
            int idx = tid + i * 256;
            int rr = idx >> 3, cc = (idx & 7) << 2;
            int gr = m0 + rr;
            int grc = (gr < M) ? gr : (M - 1);
            uint32_t dst = sAf + (uint32_t)(buf * AF_ELEMS + rr * BK + cc) * 4;
            const float* src = A + (size_t)grc * K + k0 + cc;
            int sz = (gr < M) ? 16 : 0;
            asm volatile("cp.async.cg.shared.global [%0], [%1], 16, %2;"
                         :: "r"(dst), "l"(src), "r"(sz));
        }
#pragma unroll
        for (int i = 0; i < 2; i++) {
            int idx = tid + i * 256;
            int rr = idx >> 4, cc = (idx & 15) << 3;
            uint32_t dst = sWs + (uint32_t)(buf * WS_ELEMS + rr * WS_STRIDE + cc) * 2;
            const __half* src = Wh + (size_t)(k0 + rr) * N + cc;
            asm volatile("cp.async.cg.shared.global [%0], [%1], 16;"
                         :: "r"(dst), "l"(src));
        }
        asm volatile("cp.async.commit_group;");
    };

    issue_cp(0);

    for (int t = 0; t < T; t++) {
        if (t + 1 < T) {
            issue_cp(t + 1);
            asm volatile("cp.async.wait_group 1;");
        } else {
            asm volatile("cp.async.wait_group 0;");
        }
        __syncthreads();

        const int buf = t & 1;
#pragma unroll
        for (int i = 0; i < 4; i++) {
            int idx = tid + i * 256;
            int rr = idx >> 3, cc = (idx & 7) << 2;
            float4 v = *(const float4*)(Af + buf * AF_ELEMS + rr * BK + cc);
            __half2* dst = (__half2*)(&As[rr * AS_STRIDE + cc]);
            dst[0] = __floats2half2_rn(v.x, v.y);
            dst[1] = __floats2half2_rn(v.z, v.w);
        }
        __syncthreads();

        const uint32_t sW = sWs + (uint32_t)(buf * WS_ELEMS) * 2;
#pragma unroll
        for (int ks = 0; ks < 2; ks++) {
            const int kk = ks * 16;
            uint32_t a[2][4], b[4][4];
#pragma unroll
            for (int mi = 0; mi < 2; mi++) {
                int r0 = wm * 32 + mi * 16;
                uint32_t addr = sAs + ((r0 + (lane & 15)) * AS_STRIDE
                                       + kk + ((lane >> 4) << 3)) * 2;
                ldsm_x4(a[mi], addr);
            }
#pragma unroll
            for (int p = 0; p < 4; p++) {
                int c0 = wn * 64 + p * 16;
                uint32_t addr = sW + ((kk + (lane & 15)) * WS_STRIDE
                                      + c0 + ((lane >> 4) << 3)) * 2;
                ldsm_x4_t(b[p], addr);
            }
#pragma unroll
            for (int mi = 0; mi < 2; mi++)
#pragma unroll
                for (int p = 0; p < 4; p++) {
                    mma16816(acc[mi][2 * p],     a[mi], &b[p][0]);
                    mma16816(acc[mi][2 * p + 1], a[mi], &b[p][2]);
                }
        }
        if (t + 1 < T) __syncthreads();   // protect Ws[buf] from cp(t+2)
    }

    const int rq = lane >> 2;
    const int cq = (lane & 3) << 1;
#pragma unroll
    for (int ni = 0; ni < 8; ni++) {
        int gc = wn * 64 + ni * 8 + cq;
        float2 bb = *(const float2*)(bias + gc);
#pragma unroll
        for (int mi = 0; mi < 2; mi++) {
            int r_base = m0 + wm * 32 + mi * 16 + rq;
            float* d = acc[mi][ni];
            if (r_base < M)
                *(__half2*)(C + (size_t)r_base * FEAT + gc) =
                    __floats2half2_rn(d[0] + bb.x, d[1] + bb.y);
            if (r_base + 8 < M)
                *(__half2*)(C + (size_t)(r_base + 8) * FEAT + gc) =
                    __floats2half2_rn(d[2] + bb.x, d[3] + bb.y);
        }
    }
}

// ---------------------------------------------------------------------------
// GEMM2 (exact R12/R14): fp16 A direct cp.async, W2 preconverted in smem.
// ---------------------------------------------------------------------------
__global__ __launch_bounds__(256) void gemm2_cpasync_kernel(
    const __half* __restrict__ A, const float* __restrict__ W,
    const float* __restrict__ bias, __half* __restrict__ C, int M)
{
    constexpr int K = 128, BM = 128, BK = 32, N = 128;
    constexpr int T = K / BK;
    constexpr int AS_ELEMS = BM * AS_STRIDE;

    extern __shared__ char smem_raw[];
    __half* As = (__half*)smem_raw;
    __half* Ws = (__half*)(smem_raw + 2 * AS_ELEMS * 2);

    const int tid  = threadIdx.x;
    const int lane = tid & 31;
    const int wid  = tid >> 5;
    const int wm   = wid >> 1;
    const int wn   = wid & 1;
    const int m0   = blockIdx.x * BM;

    const uint32_t sAs = (uint32_t)__cvta_generic_to_shared(As);
    const uint32_t sWs = (uint32_t)__cvta_generic_to_shared(Ws);

    float acc[2][8][4];
#pragma unroll
    for (int i = 0; i < 2; i++)
#pragma unroll
        for (int j = 0; j < 8; j++)
#pragma unroll
            for (int q = 0; q < 4; q++) acc[i][j][q] = 0.f;

    auto issue_cp = [&](int t) {
        const int k0  = t * BK;
        const int buf = t & 1;
#pragma unroll
        for (int i = 0; i < 2; i++) {
            int idx = tid + i * 256;
            int rr = idx >> 2, cc = (idx & 3) << 3;
            int gr = m0 + rr;
            int grc = (gr < M) ? gr : (M - 1);
            uint32_t dst = sAs + (uint32_t)(buf * AS_ELEMS + rr * AS_STRIDE + cc) * 2;
            const __half* src = A + (size_t)grc * K + k0 + cc;
            int sz = (gr < M) ? 16 : 0;
            asm volatile("cp.async.cg.shared.global [%0], [%1], 16, %2;"
                         :: "r"(dst), "l"(src), "r"(sz));
        }
        asm volatile("cp.async.commit_group;");
    };

    issue_cp(0);

#pragma unroll
    for (int i = 0; i < 16; i++) {
        int idx = tid + i * 256;
        int rr = idx >> 5, cc = (idx & 31) << 2;
        float4 v = *(const float4*)(W + (size_t)rr * N + cc);
        __half2* dst = (__half2*)(&Ws[rr * WS_STRIDE + cc]);
        dst[0] = __floats2half2_rn(v.x, v.y);
        dst[1] = __floats2half2_rn(v.z, v.w);
    }

    for (int t = 0; t < T; t++) {
        if (t + 1 < T) {
            issue_cp(t + 1);
            asm volatile("cp.async.wait_group 1;");
        } else {
            asm volatile("cp.async.wait_group 0;");
        }
        __syncthreads();

        const int buf = t & 1;
        const uint32_t sA = sAs + (uint32_t)(buf * AS_ELEMS) * 2;
#pragma unroll
        for (int ks = 0; ks < 2; ks++) {
            const int kk = ks * 16;
            const int kg = t * BK + kk;
            uint32_t a[2][4], b[4][4];
#pragma unroll
            for (int mi = 0; mi < 2; mi++) {
                int r0 = wm * 32 + mi * 16;
                uint32_t addr = sA + ((r0 + (lane & 15)) * AS_STRIDE
                                      + kk + ((lane >> 4) << 3)) * 2;
                ldsm_x4(a[mi], addr);
            }
#pragma unroll
            for (int p = 0; p < 4; p++) {
                int c0 = wn * 64 + p * 16;
                uint32_t addr = sWs + ((kg + (lane & 15)) * WS_STRIDE
                                       + c0 + ((lane >> 4) << 3)) * 2;
                ldsm_x4_t(b[p], addr);
            }
#pragma unroll
            for (int mi = 0; mi < 2; mi++)
#pragma unroll
                for (int p = 0; p < 4; p++) {
                    mma16816(acc[mi][2 * p],     a[mi], &b[p][0]);
                    mma16816(acc[mi][2 * p + 1], a[mi], &b[p][2]);
                }
        }
        __syncthreads();
    }

    const int rq = lane >> 2;
    const int cq = (lane & 3) << 1;
#pragma unroll
    for (int ni = 0; ni < 8; ni++) {
        int gc = wn * 64 + ni * 8 + cq;
        float2 bb = *(const float2*)(bias + gc);
#pragma unroll
        for (int mi = 0; mi < 2; mi++) {
            int r_base = m0 + wm * 32 + mi * 16 + rq;
            float* d = acc[mi][ni];
            if (r_base < M)
                *(__half2*)(C + (size_t)r_base * N + gc) =
                    __floats2half2_rn(d[0] + bb.x, d[1] + bb.y);
            if (r_base + 8 < M)
                *(__half2*)(C + (size_t)(r_base + 8) * N + gc) =
                    __floats2half2_rn(d[2] + bb.x, d[3] + bb.y);
        }
    }
}

// ---------------------------------------------------------------------------
// CSR SpMM (exact R15): warp per row; 8-deep pipelined gather; __stcs fp32 out.
// ---------------------------------------------------------------------------
template <bool OUT_HALF_RELU>
__global__ __launch_bounds__(256) void spmm_csr_kernel(
    const int* __restrict__ row_start, const int2* __restrict__ edge,
    const __half* __restrict__ H, void* __restrict__ out_, int n)
{
    int r    = blockIdx.x * 8 + (threadIdx.x >> 5);
    int lane = threadIdx.x & 31;
    if (r >= n) return;

    int s = row_start[r];
    int e = row_start[r + 1];

    float4 acc = make_float4(0.f, 0.f, 0.f, 0.f);
    const int fo = lane << 2;

    int i = s;
    for (; i + 8 <= e; i += 8) {
        int2 ev[8];
#pragma unroll
        for (int j = 0; j < 8; j++) ev[j] = edge[i + j];
        uint2 u[8];
#pragma unroll
        for (int j = 0; j < 8; j++)
            u[j] = *(const uint2*)(H + (size_t)ev[j].x * FEAT + fo);
#pragma unroll
        for (int j = 0; j < 8; j++) {
            float v = __int_as_float(ev[j].y);
            float2 h01 = __half22float2(*(const __half2*)&u[j].x);
            float2 h23 = __half22float2(*(const __half2*)&u[j].y);
            acc.x += v * h01.x; acc.y += v * h01.y;
            acc.z += v * h23.x; acc.w += v * h23.y;
        }
    }
    for (; i < e; i++) {
        int2 ev = edge[i];
        float v = __int_as_float(ev.y);
        uint2 u = *(const uint2*)(H + (size_t)ev.x * FEAT + fo);
        float2 h01 = __half22float2(*(const __half2*)&u.x);
        float2 h23 = __half22float2(*(const __half2*)&u.y);
        acc.x += v * h01.x; acc.y += v * h01.y;
        acc.z += v * h23.x; acc.w += v * h23.y;
    }

    if (OUT_HALF_RELU) {
        __half* out = (__half*)out_;
        uint2 o;
        *(__half2*)&o.x = __floats2half2_rn(fmaxf(acc.x, 0.f), fmaxf(acc.y, 0.f));
        *(__half2*)&o.y = __floats2half2_rn(fmaxf(acc.z, 0.f), fmaxf(acc.w, 0.f));
        *(uint2*)(out + (size_t)r * FEAT + fo) = o;
    } else {
        float* out = (float*)out_;
        __stcs((float4*)(out + (size_t)r * FEAT + fo), acc);   // evict-first
    }
}

// ---------------------------------------------------------------------------
extern "C" void kernel_launch(void* const* d_in, const int* in_sizes, int n_in,
                              void* d_out, int out_size)
{
    const float* X    = (const float*)d_in[0];
    const float* W1   = (const float*)d_in[1];
    const float* b1   = (const float*)d_in[2];
    const float* W2   = (const float*)d_in[3];
    const float* b2   = (const float*)d_in[4];
    const float* vals = (const float*)d_in[5];
    const int*   row  = (const int*)d_in[6];
    const int*   col  = (const int*)d_in[7];

    const int M  = in_sizes[0] / 256;   // 100000
    const int nE = in_sizes[5];         // 1600000 (divisible by 4)

    __half *H, *S1, *W1h;
    int *cnt, *row_start, *row_next, *state;
    int2 *edge;
    cudaGetSymbolAddress((void**)&H,         g_H);
    cudaGetSymbolAddress((void**)&S1,        g_S1);
    cudaGetSymbolAddress((void**)&W1h,       g_W1h);
    cudaGetSymbolAddress((void**)&cnt,       g_cnt);
    cudaGetSymbolAddress((void**)&row_start, g_row_start);
    cudaGetSymbolAddress((void**)&row_next,  g_row_next);
    cudaGetSymbolAddress((void**)&state,     g_state);
    cudaGetSymbolAddress((void**)&edge,      g_edge);
    float* out = (float*)d_out;

    const int gemm1_smem = 2 * 128 * 32 * 4
                         + 128 * AS_STRIDE * 2
                         + 2 * 32 * WS_STRIDE * 2;          // 64512
    const int gemm2_smem = 2 * 128 * AS_STRIDE * 2
                         + 128 * WS_STRIDE * 2;             // 63488

    static cudaStream_t s_side = nullptr;
    static cudaEvent_t  ev_fork = nullptr, ev_join = nullptr;
    if (s_side == nullptr) {
        cudaStreamCreateWithFlags(&s_side, cudaStreamNonBlocking);
        cudaEventCreateWithFlags(&ev_fork, cudaEventDisableTiming);
        cudaEventCreateWithFlags(&ev_join, cudaEventDisableTiming);
        cudaFuncSetAttribute(gemm1_cpasync_kernel,
                             cudaFuncAttributeMaxDynamicSharedMemorySize, gemm1_smem);
        cudaFuncSetAttribute(gemm2_cpasync_kernel,
                             cudaFuncAttributeMaxDynamicSharedMemorySize, gemm2_smem);
    }

    const int nb  = (M + SCAN_B - 1) / SCAN_B;   // 196
    const int nE4 = nE / 4;
    const int gemm_blocks = (M + 127) / 128;

    // ---- Fork: CSR build on side stream, concurrent with GEMM1 ----
    // Enqueue order keeps GEMM1 at launch index 3 (ncu captures #3).
    cudaEventRecord(ev_fork, 0);
    cudaStreamWaitEvent(s_side, ev_fork, 0);

    hist_kernel<<<(nE4 + 255) / 256, 256, 0, s_side>>>(
        (const int4*)row, nE4, cnt, state);                                     // #0
    scan_lookback_kernel<<<nb, SCAN_B, 0, s_side>>>(
        cnt, row_start, row_next, state, M);                                    // #1
    w1_convert_kernel<<<32, 256>>>(W1, W1h);                                    // #2 (main)
    gemm1_cpasync_kernel<<<gemm_blocks, 256, gemm1_smem>>>(X, W1h, b1, H, M);   // #3 (main)
    scatter_kernel<<<(nE + 511) / 512, 512, 0, s_side>>>(row, col, vals, nE,
                                                         row_next, edge);       // #4
    cudaEventRecord(ev_join, s_side);

    // ---- Dependent chain on main ----
    cudaStreamWaitEvent(0, ev_join, 0);
    spmm_csr_kernel<true><<<(M + 7) / 8, 256>>>(row_start, edge, H, S1, M);     // #5
    gemm2_cpasync_kernel<<<gemm_blocks, 256, gemm2_smem>>>(S1, W2, b2, H, M);   // #6
    spmm_csr_kernel<false><<<(M + 7) / 8, 256>>>(row_start, edge, H, out, M);   // #7
}

// round 17
// speedup vs baseline: 1.0631x; 1.0631x over previous
#include <cuda_runtime.h>
#include <cuda_fp16.h>
#include <cstdint>

// ---------------------------------------------------------------------------
// GCN: out = SpMM(relu(SpMM(X@W1+b1)) @ W2 + b2)
// R17: algebraic commute of the tail:
//   out = SpMM(A, relu(S1)) @ W2 + rowsum(A) * b2
// -> SpMM2' gathers S1 and writes T in fp16 (half the write bytes of the old
//    fp32 SpMM2) + degw; GEMM2' computes T@W2 + degw*b2 -> fp32 out (__stcs).
// All other components are the proven R12/R14 versions (3-kernel scan,
// ticket scatter, W1-preconverted cp.async GEMM1).
// ---------------------------------------------------------------------------

#define MAX_NODES 100000
#define MAX_EDGES 1600000
#define FEAT 128
#define SCAN_B 512
#define SCAN_NB ((MAX_NODES + SCAN_B - 1) / SCAN_B)

__device__ __align__(16) __half g_H  [(size_t)MAX_NODES * FEAT];  // H1, then T
__device__ __align__(16) __half g_S1 [(size_t)MAX_NODES * FEAT];  // relu(SpMM1)
__device__ __align__(16) __half g_W1h[256 * 128];                 // W1 in fp16
__device__ float g_degw[MAX_NODES];                               // rowsum(A)
__device__ int  g_cnt[MAX_NODES];
__device__ int  g_row_start[MAX_NODES + 1];
__device__ int  g_row_next[MAX_NODES];
__device__ int  g_partials[SCAN_NB];
__device__ int2 g_edge[MAX_EDGES];                 // {col, float_as_int(val)}

// ---------------------------------------------------------------------------
// CSR build (exact R12): hist (RED) -> scan1/2/3 (scan3 re-zeros cnt) ->
//                        scatter (atomic ticket)
// ---------------------------------------------------------------------------
__global__ void hist_kernel(const int* __restrict__ row, int nE, int* __restrict__ cnt)
{
    int i = blockIdx.x * blockDim.x + threadIdx.x;
    if (i < nE) atomicAdd(&cnt[row[i]], 1);        // returnless -> RED
}

__global__ void scan1_kernel(const int* __restrict__ cnt, int* __restrict__ partials, int n)
{
    __shared__ int sh[SCAN_B];
    int i = blockIdx.x * SCAN_B + threadIdx.x;
    sh[threadIdx.x] = (i < n) ? cnt[i] : 0;
    __syncthreads();
#pragma unroll
    for (int off = SCAN_B / 2; off > 0; off >>= 1) {
        if (threadIdx.x < off) sh[threadIdx.x] += sh[threadIdx.x + off];
        __syncthreads();
    }
    if (threadIdx.x == 0) partials[blockIdx.x] = sh[0];
}

__global__ void scan2_kernel(int* __restrict__ partials, int nb,
                             int* __restrict__ row_start, int n)
{
    __shared__ int sh[256];
    int tid = threadIdx.x;
    int v = (tid < nb) ? partials[tid] : 0;
    sh[tid] = v;
    __syncthreads();
#pragma unroll
    for (int off = 1; off < 256; off <<= 1) {
        int t = (tid >= off) ? sh[tid - off] : 0;
        __syncthreads();
        sh[tid] += t;
        __syncthreads();
    }
    if (tid < nb) partials[tid] = sh[tid] - v;
    if (tid == 255) row_start[n] = sh[255];
}

__global__ void scan3_kernel(int* __restrict__ cnt, const int* __restrict__ partials,
                             int* __restrict__ row_start, int* __restrict__ row_next, int n)
{
    __shared__ int sh[SCAN_B];
    int tid = threadIdx.x;
    int i = blockIdx.x * SCAN_B + tid;
    int v = (i < n) ? cnt[i] : 0;
    sh[tid] = v;
    __syncthreads();
#pragma unroll
    for (int off = 1; off < SCAN_B; off <<= 1) {
        int t = (tid >= off) ? sh[tid - off] : 0;
        __syncthreads();
        sh[tid] += t;
        __syncthreads();
    }
    if (i < n) {
        int excl = sh[tid] - v + partials[blockIdx.x];
        row_start[i] = excl;
        row_next[i]  = excl;
        cnt[i]       = 0;      // restore for next call
    }
}

__global__ void scatter_kernel(const int* __restrict__ row, const int* __restrict__ col,
                               const float* __restrict__ vals, int nE,
                               int* __restrict__ row_next, int2* __restrict__ edge)
{
    int i = blockIdx.x * blockDim.x + threadIdx.x;
    if (i < nE) {
        int r = row[i];
        int p = atomicAdd(&row_next[r], 1);
        edge[p] = make_int2(col[i], __float_as_int(vals[i]));
    }
}

// ---------------------------------------------------------------------------
// W1 fp32 -> fp16 preconvert
// ---------------------------------------------------------------------------
__global__ void w1_convert_kernel(const float* __restrict__ W, __half* __restrict__ Wh)
{
    int i = blockIdx.x * 256 + threadIdx.x;     // 0..8191
    float4 v = ((const float4*)W)[i];
    uint2 o;
    *(__half2*)&o.x = __floats2half2_rn(v.x, v.y);
    *(__half2*)&o.y = __floats2half2_rn(v.z, v.w);
    ((uint2*)Wh)[i] = o;
}

// ---------------------------------------------------------------------------
// HMMA primitives
// ---------------------------------------------------------------------------
__device__ __forceinline__ void mma16816(float* d, const uint32_t* a, const uint32_t* b)
{
    asm volatile(
        "mma.sync.aligned.m16n8k16.row.col.f32.f16.f16.f32 "
        "{%0,%1,%2,%3}, {%4,%5,%6,%7}, {%8,%9}, {%0,%1,%2,%3};\n"
        : "+f"(d[0]), "+f"(d[1]), "+f"(d[2]), "+f"(d[3])
        : "r"(a[0]), "r"(a[1]), "r"(a[2]), "r"(a[3]), "r"(b[0]), "r"(b[1]));
}

__device__ __forceinline__ void ldsm_x4(uint32_t* r, uint32_t addr)
{
    asm volatile("ldmatrix.sync.aligned.m8n8.x4.shared.b16 {%0,%1,%2,%3}, [%4];"
                 : "=r"(r[0]), "=r"(r[1]), "=r"(r[2]), "=r"(r[3]) : "r"(addr));
}

__device__ __forceinline__ void ldsm_x4_t(uint32_t* r, uint32_t addr)
{
    asm volatile("ldmatrix.sync.aligned.m8n8.x4.trans.shared.b16 {%0,%1,%2,%3}, [%4];"
                 : "=r"(r[0]), "=r"(r[1]), "=r"(r[2]), "=r"(r[3]) : "r"(addr));
}

#define AS_STRIDE 56
#define WS_STRIDE 136

// ---------------------------------------------------------------------------
// GEMM1 (exact R14, race-fixed): A fp32 staged + convert; W fp16 direct.
// ---------------------------------------------------------------------------
__global__ __launch_bounds__(256) void gemm1_cpasync_kernel(
    const float* __restrict__ A, const __half* __restrict__ Wh,
    const float* __restrict__ bias, __half* __restrict__ C, int M)
{
    constexpr int K = 256, BM = 128, BK = 32, N = 128;
    constexpr int T = K / BK;                       // 8
    constexpr int AF_ELEMS = BM * BK;
    constexpr int WS_ELEMS = BK * WS_STRIDE;

    extern __shared__ char smem_raw[];
    float*  Af = (float*)smem_raw;
    __half* As = (__half*)(smem_raw + 2 * AF_ELEMS * 4);
    __half* Ws = (__half*)(smem_raw + 2 * AF_ELEMS * 4 + BM * AS_STRIDE * 2);

    const int tid  = threadIdx.x;
    const int lane = tid & 31;
    const int wid  = tid >> 5;
    const int wm   = wid >> 1;
    const int wn   = wid & 1;
    const int m0   = blockIdx.x * BM;

    const uint32_t sAf = (uint32_t)__cvta_generic_to_shared(Af);
    const uint32_t sAs = (uint32_t)__cvta_generic_to_shared(As);
    const uint32_t sWs = (uint32_t)__cvta_generic_to_shared(Ws);

    float acc[2][8][4];
#pragma unroll
    for (int i = 0; i < 2; i++)
#pragma unroll
        for (int j = 0; j < 8; j++)
#pragma unroll
            for (int q = 0; q < 4; q++) acc[i][j][q] = 0.f;

    auto issue_cp = [&](int t) {
        const int k0  = t * BK;
        const int buf = t & 1;
#pragma unroll
        for (int i = 0; i < 4; i++) {
            int idx = tid + i * 256;
            int rr = idx >> 3, cc = (idx & 7) << 2;
            int gr = m0 + rr;
            int grc = (gr < M) ? gr : (M - 1);
            uint32_t dst = sAf + (uint32_t)(buf * AF_ELEMS + rr * BK + cc) * 4;
            const float* src = A + (size_t)grc * K + k0 + cc;
            int sz = (gr < M) ? 16 : 0;
            asm volatile("cp.async.cg.shared.global [%0], [%1], 16, %2;"
                         :: "r"(dst), "l"(src), "r"(sz));
        }
#pragma unroll
        for (int i = 0; i < 2; i++) {
            int idx = tid + i * 256;
            int rr = idx >> 4, cc = (idx & 15) << 3;
            uint32_t dst = sWs + (uint32_t)(buf * WS_ELEMS + rr * WS_STRIDE + cc) * 2;
            const __half* src = Wh + (size_t)(k0 + rr) * N + cc;
            asm volatile("cp.async.cg.shared.global [%0], [%1], 16;"
                         :: "r"(dst), "l"(src));
        }
        asm volatile("cp.async.commit_group;");
    };

    issue_cp(0);

    for (int t = 0; t < T; t++) {
        if (t + 1 < T) {
            issue_cp(t + 1);
            asm volatile("cp.async.wait_group 1;");
        } else {
            asm volatile("cp.async.wait_group 0;");
        }
        __syncthreads();

        const int buf = t & 1;
#pragma unroll
        for (int i = 0; i < 4; i++) {
            int idx = tid + i * 256;
            int rr = idx >> 3, cc = (idx & 7) << 2;
            float4 v = *(const float4*)(Af + buf * AF_ELEMS + rr * BK + cc);
            __half2* dst = (__half2*)(&As[rr * AS_STRIDE + cc]);
            dst[0] = __floats2half2_rn(v.x, v.y);
            dst[1] = __floats2half2_rn(v.z, v.w);
        }
        __syncthreads();

        const uint32_t sW = sWs + (uint32_t)(buf * WS_ELEMS) * 2;
#pragma unroll
        for (int ks = 0; ks < 2; ks++) {
            const int kk = ks * 16;
            uint32_t a[2][4], b[4][4];
#pragma unroll
            for (int mi = 0; mi < 2; mi++) {
                int r0 = wm * 32 + mi * 16;
                uint32_t addr = sAs + ((r0 + (lane & 15)) * AS_STRIDE
                                       + kk + ((lane >> 4) << 3)) * 2;
                ldsm_x4(a[mi], addr);
            }
#pragma unroll
            for (int p = 0; p < 4; p++) {
                int c0 = wn * 64 + p * 16;
                uint32_t addr = sW + ((kk + (lane & 15)) * WS_STRIDE
                                      + c0 + ((lane >> 4) << 3)) * 2;
                ldsm_x4_t(b[p], addr);
            }
#pragma unroll
            for (int mi = 0; mi < 2; mi++)
#pragma unroll
                for (int p = 0; p < 4; p++) {
                    mma16816(acc[mi][2 * p],     a[mi], &b[p][0]);
                    mma16816(acc[mi][2 * p + 1], a[mi], &b[p][2]);
                }
        }
        if (t + 1 < T) __syncthreads();   // protect Ws[buf] from cp(t+2)
    }

    const int rq = lane >> 2;
    const int cq = (lane & 3) << 1;
#pragma unroll
    for (int ni = 0; ni < 8; ni++) {
        int gc = wn * 64 + ni * 8 + cq;
        float2 bb = *(const float2*)(bias + gc);
#pragma unroll
        for (int mi = 0; mi < 2; mi++) {
            int r_base = m0 + wm * 32 + mi * 16 + rq;
            float* d = acc[mi][ni];
            if (r_base < M)
                *(__half2*)(C + (size_t)r_base * FEAT + gc) =
                    __floats2half2_rn(d[0] + bb.x, d[1] + bb.y);
            if (r_base + 8 < M)
                *(__half2*)(C + (size_t)(r_base + 8) * FEAT + gc) =
                    __floats2half2_rn(d[2] + bb.x, d[3] + bb.y);
        }
    }
}

// ---------------------------------------------------------------------------
// SpMM1 (exact R12): warp per row, gather H1 fp16, relu, write S1 fp16.
// ---------------------------------------------------------------------------
__global__ __launch_bounds__(256) void spmm1_kernel(
    const int* __restrict__ row_start, const int2* __restrict__ edge,
    const __half* __restrict__ H, __half* __restrict__ out, int n)
{
    int r    = blockIdx.x * 8 + (threadIdx.x >> 5);
    int lane = threadIdx.x & 31;
    if (r >= n) return;

    int s = row_start[r];
    int e = row_start[r + 1];

    float4 acc = make_float4(0.f, 0.f, 0.f, 0.f);
    const int fo = lane << 2;

    auto fma_edge = [&](int2 ev) {
        float v = __int_as_float(ev.y);
        uint2 u = *(const uint2*)(H + (size_t)ev.x * FEAT + fo);
        float2 h01 = __half22float2(*(const __half2*)&u.x);
        float2 h23 = __half22float2(*(const __half2*)&u.y);
        acc.x += v * h01.x; acc.y += v * h01.y;
        acc.z += v * h23.x; acc.w += v * h23.y;
    };

    int i = s;
    for (; i + 4 <= e; i += 4) {
        int2 e0 = edge[i], e1 = edge[i + 1], e2 = edge[i + 2], e3 = edge[i + 3];
        fma_edge(e0); fma_edge(e1); fma_edge(e2); fma_edge(e3);
    }
    for (; i < e; i++) fma_edge(edge[i]);

    uint2 o;
    *(__half2*)&o.x = __floats2half2_rn(fmaxf(acc.x, 0.f), fmaxf(acc.y, 0.f));
    *(__half2*)&o.y = __floats2half2_rn(fmaxf(acc.z, 0.f), fmaxf(acc.w, 0.f));
    *(uint2*)(out + (size_t)r * FEAT + fo) = o;
}

// ---------------------------------------------------------------------------
// SpMM2' (NEW): T[r] = sum v_e * S1[col_e]  (fp16 out, NO relu),
//               degw[r] = sum v_e  (fp32). Half the write bytes of old SpMM2.
// ---------------------------------------------------------------------------
__global__ __launch_bounds__(256) void spmm_t_kernel(
    const int* __restrict__ row_start, const int2* __restrict__ edge,
    const __half* __restrict__ S1, __half* __restrict__ T,
    float* __restrict__ degw, int n)
{
    int r    = blockIdx.x * 8 + (threadIdx.x >> 5);
    int lane = threadIdx.x & 31;
    if (r >= n) return;

    int s = row_start[r];
    int e = row_start[r + 1];

    float4 acc = make_float4(0.f, 0.f, 0.f, 0.f);
    float  sv  = 0.f;
    const int fo = lane << 2;

    auto fma_edge = [&](int2 ev) {
        float v = __int_as_float(ev.y);
        sv += v;
        uint2 u = *(const uint2*)(S1 + (size_t)ev.x * FEAT + fo);
        float2 h01 = __half22float2(*(const __half2*)&u.x);
        float2 h23 = __half22float2(*(const __half2*)&u.y);
        acc.x += v * h01.x; acc.y += v * h01.y;
        acc.z += v * h23.x; acc.w += v * h23.y;
    };

    int i = s;
    for (; i + 4 <= e; i += 4) {
        int2 e0 = edge[i], e1 = edge[i + 1], e2 = edge[i + 2], e3 = edge[i + 3];
        fma_edge(e0); fma_edge(e1); fma_edge(e2); fma_edge(e3);
    }
    for (; i < e; i++) fma_edge(edge[i]);

    uint2 o;
    *(__half2*)&o.x = __floats2half2_rn(acc.x, acc.y);
    *(__half2*)&o.y = __floats2half2_rn(acc.z, acc.w);
    *(uint2*)(T + (size_t)r * FEAT + fo) = o;
    if (lane == 0) degw[r] = sv;
}

// ---------------------------------------------------------------------------
// GEMM2' (NEW): out[M,128] = T[M,128] @ W2 + degw * b2   (fp32 out, __stcs)
// Structure = proven gemm2_cpasync (fp16 A direct cp.async, W2 in smem).
// ---------------------------------------------------------------------------
__global__ __launch_bounds__(256) void gemm2_out_kernel(
    const __half* __restrict__ A, const float* __restrict__ W,
    const float* __restrict__ bias, const float* __restrict__ degw,
    float* __restrict__ out, int M)
{
    constexpr int K = 128, BM = 128, BK = 32, N = 128;
    constexpr int T = K / BK;
    constexpr int AS_ELEMS = BM * AS_STRIDE;

    extern __shared__ char smem_raw[];
    __half* As = (__half*)smem_raw;
    __half* Ws = (__half*)(smem_raw + 2 * AS_ELEMS * 2);

    const int tid  = threadIdx.x;
    const int lane = tid & 31;
    const int wid  = tid >> 5;
    const int wm   = wid >> 1;
    const int wn   = wid & 1;
    const int m0   = blockIdx.x * BM;

    const uint32_t sAs = (uint32_t)__cvta_generic_to_shared(As);
    const uint32_t sWs = (uint32_t)__cvta_generic_to_shared(Ws);

    float acc[2][8][4];
#pragma unroll
    for (int i = 0; i < 2; i++)
#pragma unroll
        for (int j = 0; j < 8; j++)
#pragma unroll
            for (int q = 0; q < 4; q++) acc[i][j][q] = 0.f;

    auto issue_cp = [&](int t) {
        const int k0  = t * BK;
        const int buf = t & 1;
#pragma unroll
        for (int i = 0; i < 2; i++) {
            int idx = tid + i * 256;
            int rr = idx >> 2, cc = (idx & 3) << 3;
            int gr = m0 + rr;
            int grc = (gr < M) ? gr : (M - 1);
            uint32_t dst = sAs + (uint32_t)(buf * AS_ELEMS + rr * AS_STRIDE + cc) * 2;
            const __half* src = A + (size_t)grc * K + k0 + cc;
            int sz = (gr < M) ? 16 : 0;
            asm volatile("cp.async.cg.shared.global [%0], [%1], 16, %2;"
                         :: "r"(dst), "l"(src), "r"(sz));
        }
        asm volatile("cp.async.commit_group;");
    };

    issue_cp(0);

#pragma unroll
    for (int i = 0; i < 16; i++) {
        int idx = tid + i * 256;
        int rr = idx >> 5, cc = (idx & 31) << 2;
        float4 v = *(const float4*)(W + (size_t)rr * N + cc);
        __half2* dst = (__half2*)(&Ws[rr * WS_STRIDE + cc]);
        dst[0] = __floats2half2_rn(v.x, v.y);
        dst[1] = __floats2half2_rn(v.z, v.w);
    }

    for (int t = 0; t < T; t++) {
        if (t + 1 < T) {
            issue_cp(t + 1);
            asm volatile("cp.async.wait_group 1;");
        } else {
            asm volatile("cp.async.wait_group 0;");
        }
        __syncthreads();

        const int buf = t & 1;
        const uint32_t sA = sAs + (uint32_t)(buf * AS_ELEMS) * 2;
#pragma unroll
        for (int ks = 0; ks < 2; ks++) {
            const int kk = ks * 16;
            const int kg = t * BK + kk;
            uint32_t a[2][4], b[4][4];
#pragma unroll
            for (int mi = 0; mi < 2; mi++) {
                int r0 = wm * 32 + mi * 16;
                uint32_t addr = sA + ((r0 + (lane & 15)) * AS_STRIDE
                                      + kk + ((lane >> 4) << 3)) * 2;
                ldsm_x4(a[mi], addr);
            }
#pragma unroll
            for (int p = 0; p < 4; p++) {
                int c0 = wn * 64 + p * 16;
                uint32_t addr = sWs + ((kg + (lane & 15)) * WS_STRIDE
                                       + c0 + ((lane >> 4) << 3)) * 2;
                ldsm_x4_t(b[p], addr);
            }
#pragma unroll
            for (int mi = 0; mi < 2; mi++)
#pragma unroll
                for (int p = 0; p < 4; p++) {
                    mma16816(acc[mi][2 * p],     a[mi], &b[p][0]);
                    mma16816(acc[mi][2 * p + 1], a[mi], &b[p][2]);
                }
        }
        __syncthreads();
    }

    // epilogue: out = acc + degw[r] * b2, fp32 streamed stores
    const int rq = lane >> 2;
    const int cq = (lane & 3) << 1;
#pragma unroll
    for (int mi = 0; mi < 2; mi++) {
        int r0 = m0 + wm * 32 + mi * 16 + rq;
        int r1 = r0 + 8;
        float dw0 = (r0 < M) ? degw[r0] : 0.f;
        float dw1 = (r1 < M) ? degw[r1] : 0.f;
#pragma unroll
        for (int ni = 0; ni < 8; ni++) {
            int gc = wn * 64 + ni * 8 + cq;
            float2 bb = *(const float2*)(bias + gc);
            float* d = acc[mi][ni];
            if (r0 < M) {
                float2 o0 = make_float2(d[0] + dw0 * bb.x, d[1] + dw0 * bb.y);
                __stcs((float2*)(out + (size_t)r0 * N + gc), o0);
            }
            if (r1 < M) {
                float2 o1 = make_float2(d[2] + dw1 * bb.x, d[3] + dw1 * bb.y);
                __stcs((float2*)(out + (size_t)r1 * N + gc), o1);
            }
        }
    }
}

// ---------------------------------------------------------------------------
extern "C" void kernel_launch(void* const* d_in, const int* in_sizes, int n_in,
                              void* d_out, int out_size)
{
    const float* X    = (const float*)d_in[0];
    const float* W1   = (const float*)d_in[1];
    const float* b1   = (const float*)d_in[2];
    const float* W2   = (const float*)d_in[3];
    const float* b2   = (const float*)d_in[4];
    const float* vals = (const float*)d_in[5];
    const int*   row  = (const int*)d_in[6];
    const int*   col  = (const int*)d_in[7];

    const int M  = in_sizes[0] / 256;   // 100000
    const int nE = in_sizes[5];         // 1600000

    __half *H, *S1, *W1h;
    float *degw;
    int *cnt, *row_start, *row_next, *partials;
    int2 *edge;
    cudaGetSymbolAddress((void**)&H,         g_H);
    cudaGetSymbolAddress((void**)&S1,        g_S1);
    cudaGetSymbolAddress((void**)&W1h,       g_W1h);
    cudaGetSymbolAddress((void**)&degw,      g_degw);
    cudaGetSymbolAddress((void**)&cnt,       g_cnt);
    cudaGetSymbolAddress((void**)&row_start, g_row_start);
    cudaGetSymbolAddress((void**)&row_next,  g_row_next);
    cudaGetSymbolAddress((void**)&partials,  g_partials);
    cudaGetSymbolAddress((void**)&edge,      g_edge);
    float* out = (float*)d_out;

    const int gemm1_smem = 2 * 128 * 32 * 4
                         + 128 * AS_STRIDE * 2
                         + 2 * 32 * WS_STRIDE * 2;          // 64512
    const int gemm2_smem = 2 * 128 * AS_STRIDE * 2
                         + 128 * WS_STRIDE * 2;             // 63488

    static cudaStream_t s_side = nullptr;
    static cudaEvent_t  ev_fork = nullptr, ev_join = nullptr;
    if (s_side == nullptr) {
        cudaStreamCreateWithFlags(&s_side, cudaStreamNonBlocking);
        cudaEventCreateWithFlags(&ev_fork, cudaEventDisableTiming);
        cudaEventCreateWithFlags(&ev_join, cudaEventDisableTiming);
        cudaFuncSetAttribute(gemm1_cpasync_kernel,
                             cudaFuncAttributeMaxDynamicSharedMemorySize, gemm1_smem);
        cudaFuncSetAttribute(gemm2_out_kernel,
                             cudaFuncAttributeMaxDynamicSharedMemorySize, gemm2_smem);
    }

    const int nb = (M + SCAN_B - 1) / SCAN_B;   // 196
    const int gemm_blocks = (M + 127) / 128;

    // ---- Fork: CSR build on side stream, concurrent with GEMM1 ----
    // Enqueue order keeps GEMM1 at launch index 3 (ncu captures #3).
    cudaEventRecord(ev_fork, 0);
    cudaStreamWaitEvent(s_side, ev_fork, 0);

    hist_kernel<<<(nE + 511) / 512, 512, 0, s_side>>>(row, nE, cnt);            // #0
    scan1_kernel<<<nb, SCAN_B, 0, s_side>>>(cnt, partials, M);                  // #1
    w1_convert_kernel<<<32, 256>>>(W1, W1h);                                    // #2 (main)
    gemm1_cpasync_kernel<<<gemm_blocks, 256, gemm1_smem>>>(X, W1h, b1, H, M);   // #3 (main)
    scan2_kernel<<<1, 256, 0, s_side>>>(partials, nb, row_start, M);            // #4
    scan3_kernel<<<nb, SCAN_B, 0, s_side>>>(cnt, partials, row_start,
                                            row_next, M);                       // #5
    scatter_kernel<<<(nE + 511) / 512, 512, 0, s_side>>>(row, col, vals, nE,
                                                         row_next, edge);       // #6
    cudaEventRecord(ev_join, s_side);

    // ---- Dependent chain on main ----
    cudaStreamWaitEvent(0, ev_join, 0);
    spmm1_kernel<<<(M + 7) / 8, 256>>>(row_start, edge, H, S1, M);              // #7
    spmm_t_kernel<<<(M + 7) / 8, 256>>>(row_start, edge, S1, H, degw, M);       // #8 (T = g_H)
    gemm2_out_kernel<<<gemm_blocks, 256, gemm2_smem>>>(H, W2, b2, degw, out, M);// #9
}